// round 6
// baseline (speedup 1.0000x reference)
#include <cuda_runtime.h>
#include <cstdint>

#define BB   1024
#define NJT  16
#define NBLK 256              // 16 i-tiles(64) x 16 j-tiles(128)
#define RS   528              // SMEM row stride bytes (512 data + 16 pad)

// byte offsets in dynamic SMEM
#define S_A   0               // 64 rows x 528
#define S_B   33792           // 128 rows x 528
#define S_NI  101376          // 192 floats (norms: [0:64)=A, [64:192)=B)
#define S_NP  102144          // 192 x 9 floats (norm partials); RED aliases
#define S_RED S_NP            // 128 floats (NP dead when RED is written)
#define S_TOT 109056

__device__ float g_partial[NJT * BB];
__device__ float g_ppos[BB];
__device__ int   g_counter = 0;

__device__ __forceinline__ float frcp(float x) {
    float r;
    asm("rcp.approx.f32 %0, %1;" : "=f"(r) : "f"(x));
    return r;
}
__device__ __forceinline__ void ldsm4(uint32_t r[4], uint32_t p) {
    asm volatile("ldmatrix.sync.aligned.m8n8.x4.shared.b16 {%0,%1,%2,%3}, [%4];"
                 : "=r"(r[0]), "=r"(r[1]), "=r"(r[2]), "=r"(r[3]) : "r"(p));
}
__device__ __forceinline__ void mma_tf32(float c[4], const uint32_t a[4],
                                         uint32_t b0, uint32_t b1) {
    asm volatile(
        "mma.sync.aligned.m16n8k8.row.col.f32.tf32.tf32.f32 "
        "{%0,%1,%2,%3}, {%4,%5,%6,%7}, {%8,%9}, {%0,%1,%2,%3};"
        : "+f"(c[0]), "+f"(c[1]), "+f"(c[2]), "+f"(c[3])
        : "r"(a[0]), "r"(a[1]), "r"(a[2]), "r"(a[3]), "r"(b0), "r"(b1));
}

// ---------------------------------------------------------------------------
__global__ __launch_bounds__(128)
void contrastive_fused(const float* __restrict__ f, float* __restrict__ out) {
    extern __shared__ char smc[];
    uint32_t sb;
    asm("{ .reg .u64 t; cvta.to.shared.u64 t, %1; cvt.u32.u64 %0, t; }"
        : "=r"(sb) : "l"(smc));
    const int tid = threadIdx.x, lane = tid & 31;
    const int it = blockIdx.x >> 4, jt = blockIdx.x & 15;
    const int i0 = it * 64, j0 = jt * 128;

    // ---- Stage A (64 rows) + B (128 rows), raw fp32 row-major; fused norm
    //      quarter-partials (one row per warp-rep) ---------------------------
    float* NP = (float*)(smc + S_NP);
#pragma unroll
    for (int r = 0; r < 16; r++) {
        int idx = tid + r * 128;
        int row = idx >> 5, cb = (idx & 31) << 4;
        float4 v = *(const float4*)((const char*)f + ((size_t)(i0 + row) << 9) + cb);
        *(float4*)(smc + S_A + row * RS + cb) = v;
        float s = fmaf(v.x, v.x, fmaf(v.y, v.y, fmaf(v.z, v.z, v.w * v.w)));
        s += __shfl_xor_sync(0xffffffffu, s, 8);
        s += __shfl_xor_sync(0xffffffffu, s, 16);
        if (lane < 8) NP[row * 9 + lane] = s;
    }
#pragma unroll
    for (int r = 0; r < 32; r++) {
        int idx = tid + r * 128;
        int row = idx >> 5, cb = (idx & 31) << 4;
        float4 v = *(const float4*)((const char*)f + ((size_t)(j0 + row) << 9) + cb);
        *(float4*)(smc + S_B + row * RS + cb) = v;
        float s = fmaf(v.x, v.x, fmaf(v.y, v.y, fmaf(v.z, v.z, v.w * v.w)));
        s += __shfl_xor_sync(0xffffffffu, s, 8);
        s += __shfl_xor_sync(0xffffffffu, s, 16);
        if (lane < 8) NP[(64 + row) * 9 + lane] = s;
    }
    __syncthreads();

    // ---- Finalize norms (conflict-free: bank = (9*row + c) & 31) -----------
    {
        float* NI = (float*)(smc + S_NI);
        for (int row = tid; row < 192; row += 128) {
            const float* p = NP + row * 9;
            NI[row] = ((p[0] + p[1]) + (p[2] + p[3]))
                    + ((p[4] + p[5]) + (p[6] + p[7]));
        }
    }
    __syncthreads();

    // ---- Mainloop: 32x64 warp tiles (2x2 warp grid), ldmatrix + tf32 mma ---
    const int w = tid >> 5;
    const int wm = w >> 1, wn = w & 1;
    const int L7 = lane & 7, Lk = (lane >> 3) & 1, Lh = (lane >> 4) & 1;

    uint32_t aP0 = sb + S_A + (uint32_t)((wm * 32 + L7 + Lk * 8) * RS) + Lh * 16;
    uint32_t aP1 = aP0 + 16 * RS;
    uint32_t bP[4];
#pragma unroll
    for (int q = 0; q < 4; q++)
        bP[q] = sb + S_B + (uint32_t)((wn * 64 + q * 16 + Lh * 8 + L7) * RS) + Lk * 16;

    float acc[2][8][4];
#pragma unroll
    for (int mb = 0; mb < 2; mb++)
#pragma unroll
        for (int nb = 0; nb < 8; nb++)
#pragma unroll
            for (int x = 0; x < 4; x++) acc[mb][nb][x] = 0.f;

#pragma unroll
    for (int k8 = 0; k8 < 16; k8++) {
        uint32_t a0[4], a1[4], b0[4], b1[4], b2[4], b3[4];
        ldsm4(a0, aP0 + k8 * 32);
        ldsm4(a1, aP1 + k8 * 32);
        ldsm4(b0, bP[0] + k8 * 32);
        ldsm4(b1, bP[1] + k8 * 32);
        ldsm4(b2, bP[2] + k8 * 32);
        ldsm4(b3, bP[3] + k8 * 32);
        mma_tf32(acc[0][0], a0, b0[0], b0[1]); mma_tf32(acc[0][1], a0, b0[2], b0[3]);
        mma_tf32(acc[0][2], a0, b1[0], b1[1]); mma_tf32(acc[0][3], a0, b1[2], b1[3]);
        mma_tf32(acc[0][4], a0, b2[0], b2[1]); mma_tf32(acc[0][5], a0, b2[2], b2[3]);
        mma_tf32(acc[0][6], a0, b3[0], b3[1]); mma_tf32(acc[0][7], a0, b3[2], b3[3]);
        mma_tf32(acc[1][0], a1, b0[0], b0[1]); mma_tf32(acc[1][1], a1, b0[2], b0[3]);
        mma_tf32(acc[1][2], a1, b1[0], b1[1]); mma_tf32(acc[1][3], a1, b1[2], b1[3]);
        mma_tf32(acc[1][4], a1, b2[0], b2[1]); mma_tf32(acc[1][5], a1, b2[2], b2[3]);
        mma_tf32(acc[1][6], a1, b3[0], b3[1]); mma_tf32(acc[1][7], a1, b3[2], b3[3]);
    }

    // ---- Epilogue: probits + per-row reduction -----------------------------
    const float* NI = (const float*)(smc + S_NI);
    const int g = lane >> 2, tg = lane & 3;
    float* red = (float*)(smc + S_RED);
    __syncthreads();   // NP region about to be reused as RED
#pragma unroll
    for (int mb = 0; mb < 2; mb++) {
        int r0 = wm * 32 + mb * 16 + g;
        int gi0 = i0 + r0, gi1 = gi0 + 8;
        float n0 = 1.f + NI[r0], n1 = 1.f + NI[r0 + 8];
        float s0 = 0.f, s1 = 0.f;
#pragma unroll
        for (int nb = 0; nb < 8; nb++) {
            int cl0 = wn * 64 + nb * 8 + 2 * tg;
            int gj0 = j0 + cl0, gj1 = gj0 + 1;
            float nc0 = NI[64 + cl0], nc1 = NI[64 + cl0 + 1];

            float p00 = frcp(n0 + nc0 - 2.f * acc[mb][nb][0]);
            float p01 = frcp(n0 + nc1 - 2.f * acc[mb][nb][1]);
            float p10 = frcp(n1 + nc0 - 2.f * acc[mb][nb][2]);
            float p11 = frcp(n1 + nc1 - 2.f * acc[mb][nb][3]);

            if (gj0 == gi0) p00 = 0.f; else if (gj0 == gi0 + BB) g_ppos[gi0] = p00;
            if (gj1 == gi0) p01 = 0.f; else if (gj1 == gi0 + BB) g_ppos[gi0] = p01;
            if (gj0 == gi1) p10 = 0.f; else if (gj0 == gi1 + BB) g_ppos[gi1] = p10;
            if (gj1 == gi1) p11 = 0.f; else if (gj1 == gi1 + BB) g_ppos[gi1] = p11;

            s0 += p00 + p01;
            s1 += p10 + p11;
        }
        s0 += __shfl_xor_sync(0xffffffffu, s0, 1);
        s0 += __shfl_xor_sync(0xffffffffu, s0, 2);
        s1 += __shfl_xor_sync(0xffffffffu, s1, 1);
        s1 += __shfl_xor_sync(0xffffffffu, s1, 2);
        if (tg == 0) {
            red[wn * 64 + r0] = s0;
            red[wn * 64 + r0 + 8] = s1;
        }
    }
    __syncthreads();
    if (tid < 64)
        g_partial[jt * BB + i0 + tid] = red[tid] + red[64 + tid];

    // ---- Last-block finish (deterministic fixed-order sums) ----------------
    __shared__ int sflag;
    __syncthreads();
    if (tid == 0) {
        __threadfence();
        int old = atomicAdd(&g_counter, 1);
        sflag = (old == NBLK - 1);
    }
    __syncthreads();
    if (sflag) {
        __threadfence();
        if (tid == 0) g_counter = 0;       // reset for next graph replay
        float accl = 0.f;
#pragma unroll
        for (int m = 0; m < 8; m++) {
            int i = m * 128 + tid;
            float S = 0.f;
#pragma unroll
            for (int t = 0; t < NJT; t++) S += g_partial[t * BB + i];
            accl += __logf(S) - __logf(g_ppos[i]);
        }
#pragma unroll
        for (int o = 16; o; o >>= 1) accl += __shfl_xor_sync(0xffffffffu, accl, o);
        float* wsum = (float*)(smc + S_NI);
        if (lane == 0) wsum[tid >> 5] = accl;
        __syncthreads();
        if (tid == 0)
            out[0] = ((wsum[0] + wsum[1]) + (wsum[2] + wsum[3])) * (1.0f / (float)BB);
    }
}

// ---------------------------------------------------------------------------
extern "C" void kernel_launch(void* const* d_in, const int* in_sizes, int n_in,
                              void* d_out, int out_size) {
    const float* features = (const float*)d_in[0];
    float* out = (float*)d_out;

    cudaFuncSetAttribute(contrastive_fused,
                         cudaFuncAttributeMaxDynamicSharedMemorySize, S_TOT);
    contrastive_fused<<<NBLK, 128, S_TOT>>>(features, out);
}

// round 7
// speedup vs baseline: 1.2103x; 1.2103x over previous
#include <cuda_runtime.h>
#include <cuda_fp16.h>
#include <cstdint>

#define BB   1024
#define NJT  16
#define NBLK 128              // 8 i-tiles x 16 j-tiles of 128x128, one wave
#define RS   272              // fp16 row: 256 B data + 16 B pad

// byte offsets in dynamic SMEM
#define S_A   0               // 128 rows x 272
#define S_B   34816           // 128 rows x 272
#define S_NI  69632           // 256 floats (norms: [0:128)=A, [128:256)=B)
#define S_NP  70656           // 256 x 9 floats (norm partials); RED aliases
#define S_RED S_NP            // 4 x 128 floats (NP dead by then)
#define S_TOT 79872

__device__ float g_partial[NJT * BB];
__device__ float g_ppos[BB];
__device__ int   g_counter = 0;

__device__ __forceinline__ float frcp(float x) {
    float r;
    asm("rcp.approx.f32 %0, %1;" : "=f"(r) : "f"(x));
    return r;
}
__device__ __forceinline__ void ldsm4(uint32_t r[4], uint32_t p) {
    asm volatile("ldmatrix.sync.aligned.m8n8.x4.shared.b16 {%0,%1,%2,%3}, [%4];"
                 : "=r"(r[0]), "=r"(r[1]), "=r"(r[2]), "=r"(r[3]) : "r"(p));
}
__device__ __forceinline__ void mma_f16(float c[4], const uint32_t a[4],
                                        uint32_t b0, uint32_t b1) {
    asm volatile(
        "mma.sync.aligned.m16n8k16.row.col.f32.f16.f16.f32 "
        "{%0,%1,%2,%3}, {%4,%5,%6,%7}, {%8,%9}, {%0,%1,%2,%3};"
        : "+f"(c[0]), "+f"(c[1]), "+f"(c[2]), "+f"(c[3])
        : "r"(a[0]), "r"(a[1]), "r"(a[2]), "r"(a[3]), "r"(b0), "r"(b1));
}

// ---------------------------------------------------------------------------
__global__ __launch_bounds__(512, 1)
void contrastive_fused(const float* __restrict__ f, float* __restrict__ out) {
    extern __shared__ char smc[];
    uint32_t sb;
    asm("{ .reg .u64 t; cvta.to.shared.u64 t, %1; cvt.u32.u64 %0, t; }"
        : "=r"(sb) : "l"(smc));
    const int tid = threadIdx.x, lane = tid & 31;
    const int it = blockIdx.x >> 4, jt = blockIdx.x & 15;
    const int i0 = it * 128, j0 = jt * 128;

    // ---- Stage A/B rows as fp16 + fused norm quarter-partials --------------
    float* NP = (float*)(smc + S_NP);
#pragma unroll
    for (int r = 0; r < 8; r++) {
        int idx = tid + r * 512;
        int row = idx >> 5;                 // one row per warp per rep
        int c4 = (idx & 31) << 2;
        float4 v = *(const float4*)(f + (size_t)(i0 + row) * 128 + c4);
        __half2 h0 = __float22half2_rn(make_float2(v.x, v.y));
        __half2 h1 = __float22half2_rn(make_float2(v.z, v.w));
        *(uint2*)(smc + S_A + row * RS + c4 * 2) =
            make_uint2(*(uint32_t*)&h0, *(uint32_t*)&h1);
        float s = fmaf(v.x, v.x, fmaf(v.y, v.y, fmaf(v.z, v.z, v.w * v.w)));
        s += __shfl_xor_sync(0xffffffffu, s, 8);
        s += __shfl_xor_sync(0xffffffffu, s, 16);
        if (lane < 8) NP[row * 9 + lane] = s;
    }
#pragma unroll
    for (int r = 0; r < 8; r++) {
        int idx = tid + r * 512;
        int row = idx >> 5;
        int c4 = (idx & 31) << 2;
        float4 v = *(const float4*)(f + (size_t)(j0 + row) * 128 + c4);
        __half2 h0 = __float22half2_rn(make_float2(v.x, v.y));
        __half2 h1 = __float22half2_rn(make_float2(v.z, v.w));
        *(uint2*)(smc + S_B + row * RS + c4 * 2) =
            make_uint2(*(uint32_t*)&h0, *(uint32_t*)&h1);
        float s = fmaf(v.x, v.x, fmaf(v.y, v.y, fmaf(v.z, v.z, v.w * v.w)));
        s += __shfl_xor_sync(0xffffffffu, s, 8);
        s += __shfl_xor_sync(0xffffffffu, s, 16);
        if (lane < 8) NP[(128 + row) * 9 + lane] = s;
    }
    __syncthreads();

    // ---- Finalize norms ----------------------------------------------------
    if (tid < 256) {
        const float* p = NP + tid * 9;
        ((float*)(smc + S_NI))[tid] =
            ((p[0] + p[1]) + (p[2] + p[3])) + ((p[4] + p[5]) + (p[6] + p[7]));
    }
    __syncthreads();

    // ---- Mainloop: 32x32 per warp (4x4 warp grid), fp16 m16n8k16 -----------
    const int w = tid >> 5;
    const int wm = w >> 2, wn = w & 3;
    const int L7 = lane & 7, Lb3 = (lane >> 3) & 1, Lb4 = (lane >> 4) & 1;

    // A ldsm addrs: m0 rows+0-7@+0, m1 rows+8-15@+0, m2 rows+0-7@+16, m3 +8-15@+16
    uint32_t aP0 = sb + S_A + (uint32_t)((wm * 32 + L7 + Lb3 * 8) * RS) + Lb4 * 16;
    uint32_t aP1 = aP0 + 16 * RS;
    // B ldsm addrs: m0 rows+0-7@+0, m1 rows+0-7@+16, m2 rows+8-15@+0, m3 +8-15@+16
    uint32_t bP0 = sb + S_B + (uint32_t)((wn * 32 + L7 + Lb4 * 8) * RS) + Lb3 * 16;
    uint32_t bP1 = bP0 + 16 * RS;

    float acc[2][4][4];
#pragma unroll
    for (int mb = 0; mb < 2; mb++)
#pragma unroll
        for (int nb = 0; nb < 4; nb++)
#pragma unroll
            for (int x = 0; x < 4; x++) acc[mb][nb][x] = 0.f;

#pragma unroll
    for (int s = 0; s < 8; s++) {
        uint32_t a0[4], a1[4], b0[4], b1[4];
        ldsm4(a0, aP0 + s * 32);
        ldsm4(a1, aP1 + s * 32);
        ldsm4(b0, bP0 + s * 32);
        ldsm4(b1, bP1 + s * 32);
        mma_f16(acc[0][0], a0, b0[0], b0[1]);
        mma_f16(acc[0][1], a0, b0[2], b0[3]);
        mma_f16(acc[0][2], a0, b1[0], b1[1]);
        mma_f16(acc[0][3], a0, b1[2], b1[3]);
        mma_f16(acc[1][0], a1, b0[0], b0[1]);
        mma_f16(acc[1][1], a1, b0[2], b0[3]);
        mma_f16(acc[1][2], a1, b1[0], b1[1]);
        mma_f16(acc[1][3], a1, b1[2], b1[3]);
    }

    // ---- Epilogue: probits + per-row reduction -----------------------------
    const float* NI = (const float*)(smc + S_NI);
    const int g = lane >> 2, tg = lane & 3;
    float* red = (float*)(smc + S_RED);
    __syncthreads();   // NP about to be reused as RED
#pragma unroll
    for (int mb = 0; mb < 2; mb++) {
        int r0 = wm * 32 + mb * 16 + g;
        int gi0 = i0 + r0, gi1 = gi0 + 8;
        float n0 = 1.f + NI[r0], n1 = 1.f + NI[r0 + 8];
        float s0 = 0.f, s1 = 0.f;
#pragma unroll
        for (int nb = 0; nb < 4; nb++) {
            int cl0 = wn * 32 + nb * 8 + 2 * tg;
            int gj0 = j0 + cl0, gj1 = gj0 + 1;
            float nc0 = NI[128 + cl0], nc1 = NI[128 + cl0 + 1];

            float p00 = frcp(n0 + nc0 - 2.f * acc[mb][nb][0]);
            float p01 = frcp(n0 + nc1 - 2.f * acc[mb][nb][1]);
            float p10 = frcp(n1 + nc0 - 2.f * acc[mb][nb][2]);
            float p11 = frcp(n1 + nc1 - 2.f * acc[mb][nb][3]);

            if (gj0 == gi0) p00 = 0.f; else if (gj0 == gi0 + BB) g_ppos[gi0] = p00;
            if (gj1 == gi0) p01 = 0.f; else if (gj1 == gi0 + BB) g_ppos[gi0] = p01;
            if (gj0 == gi1) p10 = 0.f; else if (gj0 == gi1 + BB) g_ppos[gi1] = p10;
            if (gj1 == gi1) p11 = 0.f; else if (gj1 == gi1 + BB) g_ppos[gi1] = p11;

            s0 += p00 + p01;
            s1 += p10 + p11;
        }
        s0 += __shfl_xor_sync(0xffffffffu, s0, 1);
        s0 += __shfl_xor_sync(0xffffffffu, s0, 2);
        s1 += __shfl_xor_sync(0xffffffffu, s1, 1);
        s1 += __shfl_xor_sync(0xffffffffu, s1, 2);
        if (tg == 0) {
            red[wn * 128 + r0] = s0;
            red[wn * 128 + r0 + 8] = s1;
        }
    }
    __syncthreads();
    if (tid < 128)
        g_partial[jt * BB + i0 + tid] =
            (red[tid] + red[128 + tid]) + (red[256 + tid] + red[384 + tid]);

    // ---- Last-block finish (deterministic fixed-order sums) ----------------
    __shared__ int sflag;
    if (tid == 0) {
        __threadfence();
        int old = atomicAdd(&g_counter, 1);
        sflag = (old == NBLK - 1);
    }
    __syncthreads();
    if (sflag) {
        __threadfence();
        if (tid == 0) g_counter = 0;       // reset for next graph replay
        float accl = 0.f;
#pragma unroll
        for (int m = 0; m < 2; m++) {
            int i = tid * 2 + m;
            float S = 0.f;
#pragma unroll
            for (int t = 0; t < NJT; t++) S += g_partial[t * BB + i];
            accl += __logf(S) - __logf(g_ppos[i]);
        }
#pragma unroll
        for (int o = 16; o; o >>= 1) accl += __shfl_xor_sync(0xffffffffu, accl, o);
        float* wsum = (float*)(smc + S_NI);
        if (lane == 0) wsum[tid >> 5] = accl;
        __syncthreads();
        if (tid == 0) {
            float tot = 0.f;
#pragma unroll
            for (int x = 0; x < 16; x++) tot += wsum[x];
            out[0] = tot * (1.0f / (float)BB);
        }
    }
}

// ---------------------------------------------------------------------------
extern "C" void kernel_launch(void* const* d_in, const int* in_sizes, int n_in,
                              void* d_out, int out_size) {
    const float* features = (const float*)d_in[0];
    float* out = (float*)d_out;

    cudaFuncSetAttribute(contrastive_fused,
                         cudaFuncAttributeMaxDynamicSharedMemorySize, S_TOT);
    contrastive_fused<<<NBLK, 512, S_TOT>>>(features, out);
}